// round 7
// baseline (speedup 1.0000x reference)
#include <cuda_runtime.h>

#define DIM 160
#define RP  164    // padded smem row (floats), 16B-aligned
#define NB  2

// scale0: k=10 s=2 O=71 | scale1: k=20 s=5 O=25 | scale2: k=40 s=10 O=9
// sc0/sc2 touch only even z (NZ=80); sc1 all z (NZ=160)
#define O0 71
#define O1 25
#define O2 9
#define NZ0 80
#define NZ1c 160
#define NZ2 80

#define FS0 (NB*NZ0*O0*O0)
#define FS1 (NB*NZ1c*O1*O1)
#define FS2 (NB*NZ2*O2*O2)
#define OFF0 0
#define OFF1 (5*FS0)
#define OFF2 (OFF1 + 5*FS1)

#define N3_0 (NB*O0*O0*O0)
#define N3_1 (NB*O1*O1*O1)
#define N3_2 (NB*O2*O2*O2)

#define NSTRIP0 12
#define STRIP0  6
#define NT0S   (NB*NSTRIP0*O0*O0)
#define NBLK0S ((NT0S + 255) / 256)        // 473
#define NBLK1  ((N3_1 + 255) / 256)        // 123
#define NBLK2  ((N3_2 + 255) / 256)        //   6
#define TOTBLK (NBLK0S + NBLK1 + NBLK2)

#define PB0 0
#define PB1 480
#define PB2 608

__device__ float g_bufB[OFF2 + 5*FS2];   // ~20.4 MB
__device__ float g_partials[768];
__device__ unsigned int g_count = 0;

// ---------------------------------------------------------------------------
// cp.async helpers
// ---------------------------------------------------------------------------
__device__ __forceinline__ unsigned smem_u32(const void* p) {
    return (unsigned)__cvta_generic_to_shared(p);
}
__device__ __forceinline__ void cp16(unsigned dst, const void* src) {
    asm volatile("cp.async.ca.shared.global [%0], [%1], 16;" :: "r"(dst), "l"(src));
}
__device__ __forceinline__ void cp_commit() {
    asm volatile("cp.async.commit_group;");
}
template<int N>
__device__ __forceinline__ void cp_wait() {
    asm volatile("cp.async.wait_group %0;" :: "n"(N));
}

// warp w prefetches row (rb+w) of both volumes into raw[stage]
__device__ __forceinline__ void prefetch8(const float* __restrict__ x,
                                          const float* __restrict__ y,
                                          float* raw, int stage,
                                          int b, int z0, int rb, int zs,
                                          int w, int lane) {
    int z1 = zs * (rb + w);
    const float* xr = x + ((size_t)(b * DIM + z0) * DIM + z1) * DIM;
    const float* yr = y + ((size_t)(b * DIM + z0) * DIM + z1) * DIM;
    float* dx = raw + ((size_t)(stage * 2 + 0) * 8 + w) * RP;
    float* dy = raw + ((size_t)(stage * 2 + 1) * 8 + w) * RP;
#pragma unroll
    for (int i = lane; i < 40; i += 32) {
        cp16(smem_u32(dx + 4 * i), xr + 4 * i);
        cp16(smem_u32(dy + 4 * i), yr + 4 * i);
    }
}

// ---------------------------------------------------------------------------
// fused_sc1: one block per (b, z0). Streams 160 z1 rows in 20 batches.
// zbatch[8][5][25] staged per batch; acc[5][25][25] accumulated (12.5 KB).
// Output layout = [f][(b*160+z0)*25+o1)*25+o2] (same as before).
// ---------------------------------------------------------------------------
#define RAWF (2*2*8*RP)   // 5248 floats
__global__ __launch_bounds__(256) void fused_sc1(const float* __restrict__ x,
                                                 const float* __restrict__ y) {
    extern __shared__ float sm[];
    float* raw = sm;
    float* zb  = sm + RAWF;            // 8*5*25 = 1000
    float* acc = zb + 8 * 5 * O1;      // 5*25*25 = 3125

    int z0 = blockIdx.x % DIM;
    int b  = blockIdx.x / DIM;
    int w    = threadIdx.x >> 5;
    int lane = threadIdx.x & 31;

    for (int i = threadIdx.x; i < 5 * O1 * O1; i += 256) acc[i] = 0.f;

    prefetch8(x, y, raw, 0, b, z0, 0, 1, w, lane);
    cp_commit();

    for (int ib = 0; ib < 20; ib++) {
        int rb  = ib * 8;
        int cur = ib & 1;
        if (ib < 19) {
            prefetch8(x, y, raw, cur ^ 1, b, z0, rb + 8, 1, w, lane);
            cp_commit();
            cp_wait<1>();
        } else {
            cp_wait<0>();
        }
        __syncthreads();

        // stage: win5 for 8 rows x 25 windows
        if (threadIdx.x < 8 * O1) {
            int rl = threadIdx.x / O1;
            int o2 = threadIdx.x % O1;
            const float* xr = raw + ((size_t)(cur * 2 + 0) * 8 + rl) * RP;
            const float* yr = raw + ((size_t)(cur * 2 + 1) * 8 + rl) * RP;
            int base = 5 * o2;
            float a0 = 0.f, a1 = 0.f, a2 = 0.f, a3 = 0.f, a4 = 0.f;
#pragma unroll
            for (int t = 0; t < 20; t++) {
                float xv = xr[base + 2 * t];
                float yv = yr[base + 2 * t];
                a0 += xv; a1 += yv; a2 += xv * xv; a3 += yv * yv; a4 += xv * yv;
            }
            float* z = zb + (size_t)rl * 5 * O1 + o2;
            z[0 * O1] = a0; z[1 * O1] = a1; z[2 * O1] = a2;
            z[3 * O1] = a3; z[4 * O1] = a4;
        }
        __syncthreads();

        // accumulate into windows overlapping this batch
        int o1lo = (rb >= 38) ? (rb - 38 + 4) / 5 : 0;
        int o1hi = (rb + 7) / 5;  if (o1hi > O1 - 1) o1hi = O1 - 1;
        int NA = o1hi - o1lo + 1;
        int items = 5 * NA * O1;
        for (int it = threadIdx.x; it < items; it += 256) {
            int f   = it / (NA * O1);
            int rem = it % (NA * O1);
            int o1  = o1lo + rem / O1;
            int o2  = rem % O1;
            int p0  = 5 * o1;
            int lo  = p0 - rb;      if (lo < 0) lo = 0;
            int hi  = p0 + 38 - rb; if (hi > 7) hi = 7;
            lo += ((rb + lo) ^ p0) & 1;          // parity: (rb+rl-p0) even
            float a = 0.f;
            for (int rl = lo; rl <= hi; rl += 2)
                a += zb[(size_t)(rl * 5 + f) * O1 + o2];
            acc[(f * O1 + o1) * O1 + o2] += a;
        }
        __syncthreads();
    }

    for (int it = threadIdx.x; it < 5 * O1 * O1; it += 256) {
        int f = it / (O1 * O1), rem = it % (O1 * O1);
        int o1 = rem / O1, o2 = rem % O1;
        g_bufB[OFF1 + f * FS1 + (((b * NZ1c) + z0) * O1 + o1) * O1 + o2] =
            acc[(f * O1 + o1) * O1 + o2];
    }
}

// ---------------------------------------------------------------------------
// fused_sc02: one block per (b, z0i, ch). Even rows (z = 2*zi), 10 batches.
// sc0 chunk CH=36 of o2 in smem acc; sc2 (ch==0) accumulated in registers.
// ---------------------------------------------------------------------------
#define CH0 36
__global__ __launch_bounds__(256) void fused_sc02(const float* __restrict__ x,
                                                  const float* __restrict__ y) {
    extern __shared__ float sm[];
    float* raw  = sm;
    float* zb0  = sm + RAWF;                  // 8*5*36 = 1440
    float* zb2  = zb0 + 8 * 5 * CH0;          // 8*5*9  = 360
    float* acc0 = zb2 + 8 * 5 * O2;           // 5*71*36 = 12780

    int bid = blockIdx.x;
    int ch  = bid & 1;  bid >>= 1;
    int z0i = bid % NZ0;
    int b   = bid / NZ0;
    int z0  = 2 * z0i;
    int obase = ch * CH0;
    int w    = threadIdx.x >> 5;
    int lane = threadIdx.x & 31;

    for (int i = threadIdx.x; i < 5 * O0 * CH0; i += 256) acc0[i] = 0.f;
    float a2r0 = 0.f, a2r1 = 0.f;   // sc2 register accumulators (2 items/thread)

    prefetch8(x, y, raw, 0, b, z0, 0, 2, w, lane);
    cp_commit();

    for (int ib = 0; ib < 10; ib++) {
        int rb  = ib * 8;
        int cur = ib & 1;
        if (ib < 9) {
            prefetch8(x, y, raw, cur ^ 1, b, z0, rb + 8, 2, w, lane);
            cp_commit();
            cp_wait<1>();
        } else {
            cp_wait<0>();
        }
        __syncthreads();

        // stage win5: sc0 items [0,288), sc2 items [288,360) (ch0 only)
        int nit = (ch == 0) ? (8 * CH0 + 8 * O2) : (8 * CH0);
        for (int it = threadIdx.x; it < nit; it += 256) {
            if (it < 8 * CH0) {
                int rl  = it / CH0;
                int o2l = it % CH0;
                int o2  = obase + o2l;
                if (o2 < O0) {
                    const float* xr = raw + ((size_t)(cur * 2 + 0) * 8 + rl) * RP;
                    const float* yr = raw + ((size_t)(cur * 2 + 1) * 8 + rl) * RP;
                    int base = 2 * o2;
                    float a0 = 0.f, a1 = 0.f, a2 = 0.f, a3 = 0.f, a4 = 0.f;
#pragma unroll
                    for (int t = 0; t < 10; t++) {
                        float xv = xr[base + 2 * t];
                        float yv = yr[base + 2 * t];
                        a0 += xv; a1 += yv; a2 += xv * xv; a3 += yv * yv; a4 += xv * yv;
                    }
                    float* z = zb0 + (size_t)rl * 5 * CH0 + o2l;
                    z[0 * CH0] = a0; z[1 * CH0] = a1; z[2 * CH0] = a2;
                    z[3 * CH0] = a3; z[4 * CH0] = a4;
                }
            } else {
                int it2 = it - 8 * CH0;
                int rl = it2 / O2;
                int o2 = it2 % O2;
                const float* xr = raw + ((size_t)(cur * 2 + 0) * 8 + rl) * RP;
                const float* yr = raw + ((size_t)(cur * 2 + 1) * 8 + rl) * RP;
                int base = 10 * o2;
                float a0 = 0.f, a1 = 0.f, a2 = 0.f, a3 = 0.f, a4 = 0.f;
#pragma unroll
                for (int t = 0; t < 40; t++) {
                    float xv = xr[base + 2 * t];
                    float yv = yr[base + 2 * t];
                    a0 += xv; a1 += yv; a2 += xv * xv; a3 += yv * yv; a4 += xv * yv;
                }
                float* z = zb2 + (size_t)rl * 5 * O2 + o2;
                z[0 * O2] = a0; z[1 * O2] = a1; z[2 * O2] = a2;
                z[3 * O2] = a3; z[4 * O2] = a4;
            }
        }
        __syncthreads();

        // accumulate sc0: active o1 windows (taps = consecutive planes o1..o1+9)
        {
            int o1lo = rb - 9; if (o1lo < 0) o1lo = 0;
            int o1hi = rb + 7; if (o1hi > O0 - 1) o1hi = O0 - 1;
            int NA = o1hi - o1lo + 1;
            int items = 5 * NA * CH0;
            for (int it = threadIdx.x; it < items; it += 256) {
                int f   = it / (NA * CH0);
                int rem = it % (NA * CH0);
                int o1  = o1lo + rem / CH0;
                int o2l = rem % CH0;
                int lo = o1 - rb;     if (lo < 0) lo = 0;
                int hi = o1 + 9 - rb; if (hi > 7) hi = 7;
                float a = 0.f;
                for (int rl = lo; rl <= hi; rl++)
                    a += zb0[(size_t)(rl * 5 + f) * CH0 + o2l];
                acc0[(f * O0 + o1) * CH0 + o2l] += a;
            }
        }
        // accumulate sc2 in registers (ch0): planes 5*o1 .. 5*o1+39
        if (ch == 0) {
#pragma unroll
            for (int j = 0; j < 2; j++) {
                int it = threadIdx.x + 256 * j;
                if (it < 5 * O2 * O2) {
                    int f   = it / (O2 * O2);
                    int rem = it % (O2 * O2);
                    int o1  = rem / O2;
                    int o2  = rem % O2;
                    int p0  = 5 * o1;
                    int lo = p0 - rb;      if (lo < 0) lo = 0;
                    int hi = p0 + 39 - rb; if (hi > 7) hi = 7;
                    float a = 0.f;
                    for (int rl = lo; rl <= hi; rl++)
                        a += zb2[(size_t)(rl * 5 + f) * O2 + o2];
                    if (j == 0) a2r0 += a; else a2r1 += a;
                }
            }
        }
        __syncthreads();
    }

    // writeback sc0
    for (int it = threadIdx.x; it < 5 * O0 * CH0; it += 256) {
        int f   = it / (O0 * CH0);
        int rem = it % (O0 * CH0);
        int o1  = rem / CH0;
        int o2l = rem % CH0;
        int o2  = obase + o2l;
        if (o2 >= O0) continue;
        g_bufB[OFF0 + f * FS0 + (((b * NZ0) + z0i) * O0 + o1) * O0 + o2] =
            acc0[(f * O0 + o1) * CH0 + o2l];
    }
    // writeback sc2
    if (ch == 0) {
#pragma unroll
        for (int j = 0; j < 2; j++) {
            int it = threadIdx.x + 256 * j;
            if (it < 5 * O2 * O2) {
                int f   = it / (O2 * O2);
                int rem = it % (O2 * O2);
                int o1  = rem / O2;
                int o2  = rem % O2;
                g_bufB[OFF2 + f * FS2 + (((b * NZ2) + z0i) * O2 + o1) * O2 + o2] =
                    (j == 0) ? a2r0 : a2r1;
            }
        }
    }
}

// ---------------------------------------------------------------------------
// pass34 (unchanged from R6) + fused finalize
// ---------------------------------------------------------------------------
__device__ __forceinline__ float lncc_eval(float s0, float s1, float s2,
                                           float s3, float s4, float numel) {
    float xm = s0 / numel;
    float ym = s1 / numel;
    float cross = s4 - ym * s0 - xm * s1 + ym * xm * numel;
    float xvar  = s2 - 2.f * xm * s0 + xm * xm * numel;
    float yvar  = s3 - 2.f * ym * s1 + ym * ym * numel;
    return cross * cross / (xvar * yvar + 1e-5f);
}

template<int K, int O, int NZ, int B0, int TS, int OFF, int FS, int N3>
__device__ __forceinline__ float pass34_gather(int blk) {
    const float numel = (float)K * (float)K * (float)K;
    int idx = blk * 256 + threadIdx.x;
    if (idx >= N3) return 0.f;
    int o2 = idx % O;
    int r  = idx / O;
    int o1 = r % O;  r /= O;
    int o0 = r % O;
    int b  = r / O;
    int inbase = ((b * NZ + B0 * o0) * O + o1) * O + o2;
    const int tapstride = TS * O * O;
    float acc[5];
#pragma unroll
    for (int f = 0; f < 5; f++) {
        const float* p = g_bufB + OFF + f * FS + inbase;
        float a = 0.f;
#pragma unroll
        for (int t = 0; t < K; t++) a += p[t * tapstride];
        acc[f] = a;
    }
    return lncc_eval(acc[0], acc[1], acc[2], acc[3], acc[4], numel);
}

__device__ __forceinline__ float pass34_strip0(int blk) {
    int idx = blk * 256 + threadIdx.x;
    if (idx >= NT0S) return 0.f;
    int o2 = idx % O0;
    int r  = idx / O0;
    int o1 = r % O0;  r /= O0;
    int strip = r % NSTRIP0;
    int b     = r / NSTRIP0;
    int o0s = strip * STRIP0;
    int o0e = (o0s + STRIP0 < O0) ? o0s + STRIP0 : O0;
    const int PS = O0 * O0;
    int base = ((b * NZ0) * O0 + o1) * O0 + o2;
    const float* p0 = g_bufB + OFF0 + base;
    float a0 = 0.f, a1 = 0.f, a2 = 0.f, a3 = 0.f, a4 = 0.f;
    float vsum = 0.f;
    for (int z = o0s; z < o0e + 9; z++) {
        int off = z * PS;
        a0 += p0[off];
        a1 += p0[off + 1 * FS0];
        a2 += p0[off + 2 * FS0];
        a3 += p0[off + 3 * FS0];
        a4 += p0[off + 4 * FS0];
        if (z >= o0s + 9) {
            vsum += lncc_eval(a0, a1, a2, a3, a4, 1000.0f);
            int offt = (z - 9) * PS;
            a0 -= p0[offt];
            a1 -= p0[offt + 1 * FS0];
            a2 -= p0[offt + 2 * FS0];
            a3 -= p0[offt + 3 * FS0];
            a4 -= p0[offt + 4 * FS0];
        }
    }
    return vsum;
}

__global__ __launch_bounds__(256) void pass34_all(float* __restrict__ out) {
    int bb = blockIdx.x;
    float v;
    int pslot;
    if (bb < NBLK0S) {
        v = pass34_strip0(bb);
        pslot = PB0 + bb;
    } else if (bb < NBLK0S + NBLK1) {
        v = pass34_gather<20, O1, NZ1c, 5, 2, OFF1, FS1, N3_1>(bb - NBLK0S);
        pslot = PB1 + (bb - NBLK0S);
    } else {
        v = pass34_gather<40, O2, NZ2, 5, 1, OFF2, FS2, N3_2>(bb - NBLK0S - NBLK1);
        pslot = PB2 + (bb - NBLK0S - NBLK1);
    }

    __shared__ float wsum[8];
    int lane = threadIdx.x & 31;
    int wid  = threadIdx.x >> 5;
#pragma unroll
    for (int o = 16; o > 0; o >>= 1) v += __shfl_down_sync(0xffffffffu, v, o);
    if (lane == 0) wsum[wid] = v;
    __syncthreads();
    if (wid == 0) {
        v = (lane < 8) ? wsum[lane] : 0.f;
#pragma unroll
        for (int o = 4; o > 0; o >>= 1) v += __shfl_down_sync(0xffffffffu, v, o);
        if (lane == 0) g_partials[pslot] = v;
    }

    __shared__ bool isLast;
    __threadfence();
    if (threadIdx.x == 0) {
        unsigned int old = atomicAdd(&g_count, 1u);
        isLast = (old == TOTBLK - 1);
    }
    __syncthreads();
    if (!isLast) return;
    __threadfence();

    __shared__ float sh[256];
    const int   pbase[3] = {PB0, PB1, PB2};
    const int   nblk[3]  = {NBLK0S, NBLK1, NBLK2};
    const float ninv[3]  = {1.0f / N3_0, 1.0f / N3_1, 1.0f / N3_2};
    const float wsc[3]   = {0.1f, 0.3f, 0.6f};
    float total = 0.f;
    for (int sc = 0; sc < 3; sc++) {
        float a = 0.f;
        for (int i = threadIdx.x; i < nblk[sc]; i += 256) a += g_partials[pbase[sc] + i];
        sh[threadIdx.x] = a;
        __syncthreads();
#pragma unroll
        for (int st = 128; st > 0; st >>= 1) {
            if (threadIdx.x < st) sh[threadIdx.x] += sh[threadIdx.x + st];
            __syncthreads();
        }
        if (threadIdx.x == 0) total += (1.0f - sh[0] * ninv[sc]) * wsc[sc];
        __syncthreads();
    }
    if (threadIdx.x == 0) {
        out[0] = total;
        g_count = 0;
    }
}

#define SMEM_SC1  ((RAWF + 8*5*O1 + 5*O1*O1) * (int)sizeof(float))            // ~37.5 KB
#define SMEM_SC02 ((RAWF + 8*5*CH0 + 8*5*O2 + 5*O0*CH0) * (int)sizeof(float)) // ~79.3 KB

extern "C" void kernel_launch(void* const* d_in, const int* in_sizes, int n_in,
                              void* d_out, int out_size) {
    const float* x = (const float*)d_in[0];
    const float* y = (const float*)d_in[1];
    float* out = (float*)d_out;

    cudaFuncSetAttribute(fused_sc1,
                         cudaFuncAttributeMaxDynamicSharedMemorySize, SMEM_SC1);
    cudaFuncSetAttribute(fused_sc02,
                         cudaFuncAttributeMaxDynamicSharedMemorySize, SMEM_SC02);

    fused_sc1 <<<NB * DIM,      256, SMEM_SC1 >>>(x, y);
    fused_sc02<<<NB * NZ0 * 2,  256, SMEM_SC02>>>(x, y);
    pass34_all<<<TOTBLK, 256>>>(out);
}

// round 8
// speedup vs baseline: 2.0934x; 2.0934x over previous
#include <cuda_runtime.h>

#define DIM  160
#define RP   164   // padded smem row (floats); 656B = 41*16 -> 16B aligned
#define NB   2

// scale0: k=10 s=2 O=71 | scale1: k=20 s=5 O=25 | scale2: k=40 s=10 O=9
// sc0/sc2 touch only even z (NZ=80); sc1 all z (NZ=160)
#define O0 71
#define O1 25
#define O2 9
#define NZ0 80
#define NZ1c 160
#define NZ2 80

#define FS0 (NB*NZ0*O0*O0)
#define FS1 (NB*NZ1c*O1*O1)
#define FS2 (NB*NZ2*O2*O2)
#define OFF0 0
#define OFF1 (5*FS0)
#define OFF2 (OFF1 + 5*FS1)

#define N3_0 (NB*O0*O0*O0)
#define N3_1 (NB*O1*O1*O1)
#define N3_2 (NB*O2*O2*O2)

#define NSTRIP0 12
#define STRIP0  6
#define NT0S   (NB*NSTRIP0*O0*O0)
#define NBLK0S ((NT0S + 255) / 256)        // 473
#define NBLK1  ((N3_1 + 255) / 256)        // 123
#define NBLK2  ((N3_2 + 255) / 256)        //   6
#define TOTBLK (NBLK0S + NBLK1 + NBLK2)

#define PB0 0
#define PB1 480
#define PB2 608

__device__ float g_bufB[OFF2 + 5*FS2];   // ~20.4 MB
__device__ float g_partials[768];
__device__ unsigned int g_count = 0;

// fused grid: sc1 first (heaviest per block), then merged sc0+sc2
#define G1  (NB*NZ1c)      // 320
#define G02 (NB*NZ0*2)     // 320 (CH0=36, 2 chunks)
#define GALL (G1 + G02)

#define RAWF (2*2*8*RP)    // 2 stages x 2 vols x 8 rows = 5248 floats

// sc1 smem: zwin 160*5*25 (20000) + raw 5248 = 25248 floats = 100,992 B (max)
#define SMEM_ALL ((NZ1c*5*O1 + RAWF) * (int)sizeof(float))

// ---------------------------------------------------------------------------
// cp.async helpers
// ---------------------------------------------------------------------------
__device__ __forceinline__ unsigned smem_u32(const void* p) {
    return (unsigned)__cvta_generic_to_shared(p);
}
__device__ __forceinline__ void cp16(unsigned dst, const void* src) {
    asm volatile("cp.async.ca.shared.global [%0], [%1], 16;" :: "r"(dst), "l"(src));
}
__device__ __forceinline__ void cp_commit() {
    asm volatile("cp.async.commit_group;");
}
template<int N>
__device__ __forceinline__ void cp_wait() {
    asm volatile("cp.async.wait_group %0;" :: "n"(N));
}

// warp w prefetches row (rb+w) (z1 = zs*(rb+w)) of both volumes into raw[stage]
__device__ __forceinline__ void prefetch8(const float* __restrict__ x,
                                          const float* __restrict__ y,
                                          float* raw, int stage,
                                          int b, int z0, int rb, int zs,
                                          int w, int lane) {
    int z1 = zs * (rb + w);
    const float* xr = x + ((size_t)(b * DIM + z0) * DIM + z1) * DIM;
    const float* yr = y + ((size_t)(b * DIM + z0) * DIM + z1) * DIM;
    float* dx = raw + ((size_t)(stage * 2 + 0) * 8 + w) * RP;
    float* dy = raw + ((size_t)(stage * 2 + 1) * 8 + w) * RP;
#pragma unroll
    for (int i = lane; i < 40; i += 32) {
        cp16(smem_u32(dx + 4 * i), xr + 4 * i);
        cp16(smem_u32(dy + 4 * i), yr + 4 * i);
    }
}

// window sum of 5 field products over K taps (taps step 2 in z2)
template<int K>
__device__ __forceinline__ void win5(const float* xr, const float* yr, int z2s,
                                     float* out, int stride) {
    float a0 = 0.f, a1 = 0.f, a2 = 0.f, a3 = 0.f, a4 = 0.f;
#pragma unroll
    for (int t = 0; t < K; t++) {
        float xv = xr[z2s + 2 * t];
        float yv = yr[z2s + 2 * t];
        a0 += xv; a1 += yv; a2 += xv * xv; a3 += yv * yv; a4 += xv * yv;
    }
    out[0 * stride] = a0;
    out[1 * stride] = a1;
    out[2 * stride] = a2;
    out[3 * stride] = a3;
    out[4 * stride] = a4;
}

// ---------------------------------------------------------------------------
// sc1 body: K=20 S=5 O=25, NZ=160, ZS=1. zwin[160][5][25]; taps = 5*o1 + 2t.
// ---------------------------------------------------------------------------
__device__ __forceinline__ void body_sc1(int bid, const float* __restrict__ x,
                                         const float* __restrict__ y, float* sm) {
    const int O = O1, NZ = NZ1c;
    float* zwin = sm;                    // [NZ][5][O]
    float* raw  = sm + NZ * 5 * O;

    int z0 = bid % NZ;
    int b  = bid / NZ;
    int w    = threadIdx.x >> 5;
    int lane = threadIdx.x & 31;

    prefetch8(x, y, raw, 0, b, z0, 0, 1, w, lane);
    cp_commit();

    for (int ib = 0; ib < NZ / 8; ib++) {
        int rb  = ib * 8;
        int cur = ib & 1;
        if (ib < NZ / 8 - 1) {
            prefetch8(x, y, raw, cur ^ 1, b, z0, rb + 8, 1, w, lane);
            cp_commit();
            cp_wait<1>();
        } else {
            cp_wait<0>();
        }
        __syncthreads();
        if (threadIdx.x < 8 * O) {
            int rl = threadIdx.x / O;
            int o2 = threadIdx.x % O;
            const float* xr = raw + ((size_t)(cur * 2 + 0) * 8 + rl) * RP;
            const float* yr = raw + ((size_t)(cur * 2 + 1) * 8 + rl) * RP;
            win5<20>(xr, yr, 5 * o2, zwin + (size_t)(rb + rl) * 5 * O + o2, O);
        }
        __syncthreads();   // done reading raw[cur] before it is refilled
    }

    const int ITEMS = 5 * O * O;
    for (int item = threadIdx.x; item < ITEMS; item += 256) {
        int f   = item / (O * O);
        int rem = item % (O * O);
        int o1  = rem / O;
        int o2  = rem % O;
        float acc = 0.f;
#pragma unroll
        for (int t = 0; t < 20; t++)
            acc += zwin[(size_t)(5 * o1 + 2 * t) * 5 * O + f * O + o2];
        g_bufB[OFF1 + f * FS1 + (((b * NZ) + z0) * O + o1) * O + o2] = acc;
    }
}

// ---------------------------------------------------------------------------
// merged sc0+sc2 body: even planes (z = 2*zi). CH0=36, 2 chunks.
// zwin0[80][5][36]; zwin2[80][5][9] (chunk 0 only).
// ---------------------------------------------------------------------------
#define CH0 36
__device__ __forceinline__ void body_sc02(int bid, const float* __restrict__ x,
                                          const float* __restrict__ y, float* sm) {
    const int NZ = 80;
    float* zwin0 = sm;                          // [80][5][CH0]
    float* zwin2 = sm + NZ * 5 * CH0;           // [80][5][9]
    float* raw   = zwin2 + NZ * 5 * O2;

    int ch  = bid & 1;  bid >>= 1;
    int z0i = bid % NZ;
    int b   = bid / NZ;
    int z0  = 2 * z0i;
    int obase = ch * CH0;
    int w    = threadIdx.x >> 5;
    int lane = threadIdx.x & 31;

    prefetch8(x, y, raw, 0, b, z0, 0, 2, w, lane);
    cp_commit();

    for (int ib = 0; ib < NZ / 8; ib++) {
        int rb  = ib * 8;
        int cur = ib & 1;
        if (ib < NZ / 8 - 1) {
            prefetch8(x, y, raw, cur ^ 1, b, z0, rb + 8, 2, w, lane);
            cp_commit();
            cp_wait<1>();
        } else {
            cp_wait<0>();
        }
        __syncthreads();

        int nit = (ch == 0) ? (8 * CH0 + 8 * O2) : (8 * CH0);
        for (int it = threadIdx.x; it < nit; it += 256) {
            if (it < 8 * CH0) {
                int rl  = it / CH0;
                int o2l = it % CH0;
                int o2  = obase + o2l;
                if (o2 < O0) {
                    const float* xr = raw + ((size_t)(cur * 2 + 0) * 8 + rl) * RP;
                    const float* yr = raw + ((size_t)(cur * 2 + 1) * 8 + rl) * RP;
                    win5<10>(xr, yr, 2 * o2,
                             zwin0 + (size_t)(rb + rl) * 5 * CH0 + o2l, CH0);
                }
            } else {
                int it2 = it - 8 * CH0;
                int rl = it2 / O2;
                int o2 = it2 % O2;
                const float* xr = raw + ((size_t)(cur * 2 + 0) * 8 + rl) * RP;
                const float* yr = raw + ((size_t)(cur * 2 + 1) * 8 + rl) * RP;
                win5<40>(xr, yr, 10 * o2,
                         zwin2 + (size_t)(rb + rl) * 5 * O2 + o2, O2);
            }
        }
        __syncthreads();
    }

    // phase2 sc0: plane idx = o1 + t
    {
        const int ITEMS = 5 * O0 * CH0;
        for (int item = threadIdx.x; item < ITEMS; item += 256) {
            int f   = item / (O0 * CH0);
            int rem = item % (O0 * CH0);
            int o1  = rem / CH0;
            int o2l = rem % CH0;
            int o2  = obase + o2l;
            if (o2 >= O0) continue;
            float acc = 0.f;
#pragma unroll
            for (int t = 0; t < 10; t++)
                acc += zwin0[(size_t)(o1 + t) * 5 * CH0 + f * CH0 + o2l];
            g_bufB[OFF0 + f * FS0 + (((b * NZ) + z0i) * O0 + o1) * O0 + o2] = acc;
        }
    }
    // phase2 sc2: plane idx = 5*o1 + t (chunk 0 only)
    if (ch == 0) {
        const int ITEMS = 5 * O2 * O2;
        for (int item = threadIdx.x; item < ITEMS; item += 256) {
            int f   = item / (O2 * O2);
            int rem = item % (O2 * O2);
            int o1  = rem / O2;
            int o2  = rem % O2;
            float acc = 0.f;
#pragma unroll
            for (int t = 0; t < 40; t++)
                acc += zwin2[(size_t)(5 * o1 + t) * 5 * O2 + f * O2 + o2];
            g_bufB[OFF2 + f * FS2 + (((b * NZ) + z0i) * O2 + o1) * O2 + o2] = acc;
        }
    }
}

__global__ __launch_bounds__(256) void fused_all(const float* __restrict__ x,
                                                 const float* __restrict__ y) {
    extern __shared__ float sm[];
    int b = blockIdx.x;
    if (b < G1) body_sc1(b, x, y, sm);
    else        body_sc02(b - G1, x, y, sm);
}

// ---------------------------------------------------------------------------
// pass34 (R6 variant) + fused finalize
// ---------------------------------------------------------------------------
__device__ __forceinline__ float lncc_eval(float s0, float s1, float s2,
                                           float s3, float s4, float numel) {
    float xm = s0 / numel;
    float ym = s1 / numel;
    float cross = s4 - ym * s0 - xm * s1 + ym * xm * numel;
    float xvar  = s2 - 2.f * xm * s0 + xm * xm * numel;
    float yvar  = s3 - 2.f * ym * s1 + ym * ym * numel;
    return cross * cross / (xvar * yvar + 1e-5f);
}

template<int K, int O, int NZ, int B0, int TS, int OFF, int FS, int N3>
__device__ __forceinline__ float pass34_gather(int blk) {
    const float numel = (float)K * (float)K * (float)K;
    int idx = blk * 256 + threadIdx.x;
    if (idx >= N3) return 0.f;
    int o2 = idx % O;
    int r  = idx / O;
    int o1 = r % O;  r /= O;
    int o0 = r % O;
    int b  = r / O;
    int inbase = ((b * NZ + B0 * o0) * O + o1) * O + o2;
    const int tapstride = TS * O * O;
    float acc[5];
#pragma unroll
    for (int f = 0; f < 5; f++) {
        const float* p = g_bufB + OFF + f * FS + inbase;
        float a = 0.f;
#pragma unroll
        for (int t = 0; t < K; t++) a += p[t * tapstride];
        acc[f] = a;
    }
    return lncc_eval(acc[0], acc[1], acc[2], acc[3], acc[4], numel);
}

__device__ __forceinline__ float pass34_strip0(int blk) {
    int idx = blk * 256 + threadIdx.x;
    if (idx >= NT0S) return 0.f;
    int o2 = idx % O0;
    int r  = idx / O0;
    int o1 = r % O0;  r /= O0;
    int strip = r % NSTRIP0;
    int b     = r / NSTRIP0;
    int o0s = strip * STRIP0;
    int o0e = (o0s + STRIP0 < O0) ? o0s + STRIP0 : O0;
    const int PS = O0 * O0;
    int base = ((b * NZ0) * O0 + o1) * O0 + o2;
    const float* p0 = g_bufB + OFF0 + base;
    float a0 = 0.f, a1 = 0.f, a2 = 0.f, a3 = 0.f, a4 = 0.f;
    float vsum = 0.f;
    for (int z = o0s; z < o0e + 9; z++) {
        int off = z * PS;
        a0 += p0[off];
        a1 += p0[off + 1 * FS0];
        a2 += p0[off + 2 * FS0];
        a3 += p0[off + 3 * FS0];
        a4 += p0[off + 4 * FS0];
        if (z >= o0s + 9) {
            vsum += lncc_eval(a0, a1, a2, a3, a4, 1000.0f);
            int offt = (z - 9) * PS;
            a0 -= p0[offt];
            a1 -= p0[offt + 1 * FS0];
            a2 -= p0[offt + 2 * FS0];
            a3 -= p0[offt + 3 * FS0];
            a4 -= p0[offt + 4 * FS0];
        }
    }
    return vsum;
}

__global__ __launch_bounds__(256) void pass34_all(float* __restrict__ out) {
    int bb = blockIdx.x;
    float v;
    int pslot;
    if (bb < NBLK0S) {
        v = pass34_strip0(bb);
        pslot = PB0 + bb;
    } else if (bb < NBLK0S + NBLK1) {
        v = pass34_gather<20, O1, NZ1c, 5, 2, OFF1, FS1, N3_1>(bb - NBLK0S);
        pslot = PB1 + (bb - NBLK0S);
    } else {
        v = pass34_gather<40, O2, NZ2, 5, 1, OFF2, FS2, N3_2>(bb - NBLK0S - NBLK1);
        pslot = PB2 + (bb - NBLK0S - NBLK1);
    }

    __shared__ float wsum[8];
    int lane = threadIdx.x & 31;
    int wid  = threadIdx.x >> 5;
#pragma unroll
    for (int o = 16; o > 0; o >>= 1) v += __shfl_down_sync(0xffffffffu, v, o);
    if (lane == 0) wsum[wid] = v;
    __syncthreads();
    if (wid == 0) {
        v = (lane < 8) ? wsum[lane] : 0.f;
#pragma unroll
        for (int o = 4; o > 0; o >>= 1) v += __shfl_down_sync(0xffffffffu, v, o);
        if (lane == 0) g_partials[pslot] = v;
    }

    __shared__ bool isLast;
    __threadfence();
    if (threadIdx.x == 0) {
        unsigned int old = atomicAdd(&g_count, 1u);
        isLast = (old == TOTBLK - 1);
    }
    __syncthreads();
    if (!isLast) return;
    __threadfence();

    __shared__ float sh[256];
    const int   pbase[3] = {PB0, PB1, PB2};
    const int   nblk[3]  = {NBLK0S, NBLK1, NBLK2};
    const float ninv[3]  = {1.0f / N3_0, 1.0f / N3_1, 1.0f / N3_2};
    const float wsc[3]   = {0.1f, 0.3f, 0.6f};
    float total = 0.f;
    for (int sc = 0; sc < 3; sc++) {
        float a = 0.f;
        for (int i = threadIdx.x; i < nblk[sc]; i += 256) a += g_partials[pbase[sc] + i];
        sh[threadIdx.x] = a;
        __syncthreads();
#pragma unroll
        for (int st = 128; st > 0; st >>= 1) {
            if (threadIdx.x < st) sh[threadIdx.x] += sh[threadIdx.x + st];
            __syncthreads();
        }
        if (threadIdx.x == 0) total += (1.0f - sh[0] * ninv[sc]) * wsc[sc];
        __syncthreads();
    }
    if (threadIdx.x == 0) {
        out[0] = total;
        g_count = 0;
    }
}

extern "C" void kernel_launch(void* const* d_in, const int* in_sizes, int n_in,
                              void* d_out, int out_size) {
    const float* x = (const float*)d_in[0];
    const float* y = (const float*)d_in[1];
    float* out = (float*)d_out;

    cudaFuncSetAttribute(fused_all,
                         cudaFuncAttributeMaxDynamicSharedMemorySize, SMEM_ALL);

    fused_all<<<GALL, 256, SMEM_ALL>>>(x, y);
    pass34_all<<<TOTBLK, 256>>>(out);
}

// round 9
// speedup vs baseline: 2.2404x; 1.0702x over previous
#include <cuda_runtime.h>

#define DIM  160
#define RP   164   // padded smem row (floats); 656B = 41*16
#define NB   2

// scale0: k=10 s=2 O=71 | scale1: k=20 s=5 O=25 | scale2: k=40 s=10 O=9
// sc0/sc2 touch only even z (NZ=80); sc1 all z (NZ=160)
#define O0 71
#define O1 25
#define O2 9
#define NZ0 80
#define NZ1c 160
#define NZ2 80

#define FS0 (NB*NZ0*O0*O0)
#define FS1 (NB*NZ1c*O1*O1)
#define FS2 (NB*NZ2*O2*O2)
#define OFF0 0
#define OFF1 (5*FS0)
#define OFF2 (OFF1 + 5*FS1)

#define N3_0 (NB*O0*O0*O0)
#define N3_1 (NB*O1*O1*O1)
#define N3_2 (NB*O2*O2*O2)

// pass34: sc0 strips of 3 outputs, 24 strips
#define NSTRIP0 24
#define STRIP0  3
#define NT0S   (NB*NSTRIP0*O0*O0)          // 241,968
#define NBLK0S ((NT0S + 255) / 256)        // 946
#define NBLK1  ((N3_1 + 255) / 256)        // 123
#define NBLK2  ((N3_2 + 255) / 256)        //   6
#define TOTBLK (NBLK0S + NBLK1 + NBLK2)    // 1075

#define PB0 0
#define PB1 960
#define PB2 1088

__device__ float g_bufB[OFF2 + 5*FS2];   // ~20.4 MB
__device__ float g_partials[1280];
__device__ unsigned int g_count = 0;

// fused grid: sc1 first, then merged sc0+sc2 (CH0=36, 2 chunks)
#define G1  (NB*NZ1c)      // 320
#define G02 (NB*NZ0*2)     // 320
#define GALL (G1 + G02)

// raw staging: 16 rows x 2 vols x RP floats = 5248 floats (single stage)
#define RAWF (2*16*RP)

// sc1 smem: zwin 160*5*25 (20000) + raw 5248 = 25248 floats = 100,992 B (max)
#define SMEM_ALL ((NZ1c*5*O1 + RAWF) * (int)sizeof(float))

// window sum of 5 field products over K taps (taps step 2 in z2)
template<int K>
__device__ __forceinline__ void win5(const float* xr, const float* yr, int z2s,
                                     float* out, int stride) {
    float a0 = 0.f, a1 = 0.f, a2 = 0.f, a3 = 0.f, a4 = 0.f;
#pragma unroll
    for (int t = 0; t < K; t++) {
        float xv = xr[z2s + 2 * t];
        float yv = yr[z2s + 2 * t];
        a0 += xv; a1 += yv; a2 += xv * xv; a3 += yv * yv; a4 += xv * yv;
    }
    out[0 * stride] = a0;
    out[1 * stride] = a1;
    out[2 * stride] = a2;
    out[3 * stride] = a3;
    out[4 * stride] = a4;
}

// load one 160-float row into 2 float4 regs per lane (lanes 0-7 carry 2nd)
__device__ __forceinline__ void ldrow(const float* __restrict__ p, int lane,
                                      float4& r0, float4& r1) {
    const float4* q = (const float4*)p;
    r0 = q[lane];
    if (lane < 8) r1 = q[32 + lane];
}
__device__ __forceinline__ void strow(float* d, int lane,
                                      const float4& r0, const float4& r1) {
    float4* q = (float4*)d;
    q[lane] = r0;
    if (lane < 8) q[32 + lane] = r1;
}

// ---------------------------------------------------------------------------
// sc1 body: 512 threads, 10 batches of 16 rows, register double-buffering.
// zwin[160][5][25]; phase2 taps = planes 5*o1 + 2t.
// ---------------------------------------------------------------------------
__device__ __forceinline__ void body_sc1(int bid, const float* __restrict__ x,
                                         const float* __restrict__ y, float* sm) {
    const int O = O1, NZ = NZ1c;
    float* zwin = sm;                    // [NZ][5][O]
    float* raw  = sm + NZ * 5 * O;       // x rows [16][RP], then y rows [16][RP]

    int z0 = bid % NZ;
    int b  = bid / NZ;
    int w    = threadIdx.x >> 5;         // 0..15
    int lane = threadIdx.x & 31;
    const float* xbase = x + (size_t)(b * DIM + z0) * DIM * DIM;
    const float* ybase = y + (size_t)(b * DIM + z0) * DIM * DIM;

    float4 fx0, fx1, fy0, fy1;
    ldrow(xbase + (size_t)w * DIM, lane, fx0, fx1);
    ldrow(ybase + (size_t)w * DIM, lane, fy0, fy1);

    for (int ib = 0; ib < 10; ib++) {
        __syncthreads();                          // prev batch consumed
        strow(raw + w * RP,        lane, fx0, fx1);
        strow(raw + (16 + w) * RP, lane, fy0, fy1);
        if (ib < 9) {
            int z1 = (ib + 1) * 16 + w;
            ldrow(xbase + (size_t)z1 * DIM, lane, fx0, fx1);
            ldrow(ybase + (size_t)z1 * DIM, lane, fy0, fy1);
        }
        __syncthreads();                          // rows visible
        if (threadIdx.x < 16 * O) {
            int rl = threadIdx.x / O;
            int o2 = threadIdx.x % O;
            win5<20>(raw + rl * RP, raw + (16 + rl) * RP, 5 * o2,
                     zwin + (size_t)(ib * 16 + rl) * 5 * O + o2, O);
        }
    }
    __syncthreads();

    const int ITEMS = 5 * O * O;
    for (int item = threadIdx.x; item < ITEMS; item += 512) {
        int f   = item / (O * O);
        int rem = item % (O * O);
        int o1  = rem / O;
        int o2  = rem % O;
        float acc = 0.f;
#pragma unroll
        for (int t = 0; t < 20; t++)
            acc += zwin[(size_t)(5 * o1 + 2 * t) * 5 * O + f * O + o2];
        g_bufB[OFF1 + f * FS1 + (((b * NZ) + z0) * O + o1) * O + o2] = acc;
    }
}

// ---------------------------------------------------------------------------
// merged sc0+sc2 body: 512 threads, 5 batches of 16 even rows.
// zwin0[80][5][36]; zwin2[80][5][9] (chunk 0 only).
// ---------------------------------------------------------------------------
#define CH0 36
__device__ __forceinline__ void body_sc02(int bid, const float* __restrict__ x,
                                          const float* __restrict__ y, float* sm) {
    const int NZ = 80;
    float* zwin0 = sm;                          // [80][5][CH0]
    float* zwin2 = sm + NZ * 5 * CH0;           // [80][5][9]
    float* raw   = zwin2 + NZ * 5 * O2;

    int ch  = bid & 1;  bid >>= 1;
    int z0i = bid % NZ;
    int b   = bid / NZ;
    int z0  = 2 * z0i;
    int obase = ch * CH0;
    int w    = threadIdx.x >> 5;
    int lane = threadIdx.x & 31;
    const float* xbase = x + (size_t)(b * DIM + z0) * DIM * DIM;
    const float* ybase = y + (size_t)(b * DIM + z0) * DIM * DIM;

    float4 fx0, fx1, fy0, fy1;
    ldrow(xbase + (size_t)(2 * w) * DIM, lane, fx0, fx1);
    ldrow(ybase + (size_t)(2 * w) * DIM, lane, fy0, fy1);

    for (int ib = 0; ib < 5; ib++) {
        int rb = ib * 16;
        __syncthreads();
        strow(raw + w * RP,        lane, fx0, fx1);
        strow(raw + (16 + w) * RP, lane, fy0, fy1);
        if (ib < 4) {
            int z1 = 2 * (rb + 16 + w);
            ldrow(xbase + (size_t)z1 * DIM, lane, fx0, fx1);
            ldrow(ybase + (size_t)z1 * DIM, lane, fy0, fy1);
        }
        __syncthreads();

        int nit = (ch == 0) ? (16 * CH0 + 16 * O2) : (16 * CH0);
        for (int it = threadIdx.x; it < nit; it += 512) {
            if (it < 16 * CH0) {
                int rl  = it / CH0;
                int o2l = it % CH0;
                int o2  = obase + o2l;
                if (o2 < O0)
                    win5<10>(raw + rl * RP, raw + (16 + rl) * RP, 2 * o2,
                             zwin0 + (size_t)(rb + rl) * 5 * CH0 + o2l, CH0);
            } else {
                int it2 = it - 16 * CH0;
                int rl = it2 / O2;
                int o2 = it2 % O2;
                win5<40>(raw + rl * RP, raw + (16 + rl) * RP, 10 * o2,
                         zwin2 + (size_t)(rb + rl) * 5 * O2 + o2, O2);
            }
        }
    }
    __syncthreads();

    // phase2 sc0: plane idx = o1 + t
    {
        const int ITEMS = 5 * O0 * CH0;
        for (int item = threadIdx.x; item < ITEMS; item += 512) {
            int f   = item / (O0 * CH0);
            int rem = item % (O0 * CH0);
            int o1  = rem / CH0;
            int o2l = rem % CH0;
            int o2  = obase + o2l;
            if (o2 >= O0) continue;
            float acc = 0.f;
#pragma unroll
            for (int t = 0; t < 10; t++)
                acc += zwin0[(size_t)(o1 + t) * 5 * CH0 + f * CH0 + o2l];
            g_bufB[OFF0 + f * FS0 + (((b * NZ) + z0i) * O0 + o1) * O0 + o2] = acc;
        }
    }
    // phase2 sc2: plane idx = 5*o1 + t (chunk 0 only)
    if (ch == 0) {
        const int ITEMS = 5 * O2 * O2;
        for (int item = threadIdx.x; item < ITEMS; item += 512) {
            int f   = item / (O2 * O2);
            int rem = item % (O2 * O2);
            int o1  = rem / O2;
            int o2  = rem % O2;
            float acc = 0.f;
#pragma unroll
            for (int t = 0; t < 40; t++)
                acc += zwin2[(size_t)(5 * o1 + t) * 5 * O2 + f * O2 + o2];
            g_bufB[OFF2 + f * FS2 + (((b * NZ) + z0i) * O2 + o1) * O2 + o2] = acc;
        }
    }
}

__global__ __launch_bounds__(512) void fused_all(const float* __restrict__ x,
                                                 const float* __restrict__ y) {
    extern __shared__ float sm[];
    int b = blockIdx.x;
    if (b < G1) body_sc1(b, x, y, sm);
    else        body_sc02(b - G1, x, y, sm);
}

// ---------------------------------------------------------------------------
// pass34 + fused finalize
// ---------------------------------------------------------------------------
__device__ __forceinline__ float lncc_eval(float s0, float s1, float s2,
                                           float s3, float s4, float numel) {
    float xm = s0 / numel;
    float ym = s1 / numel;
    float cross = s4 - ym * s0 - xm * s1 + ym * xm * numel;
    float xvar  = s2 - 2.f * xm * s0 + xm * xm * numel;
    float yvar  = s3 - 2.f * ym * s1 + ym * ym * numel;
    return cross * cross / (xvar * yvar + 1e-5f);
}

template<int K, int O, int NZ, int B0, int TS, int OFF, int FS, int N3>
__device__ __forceinline__ float pass34_gather(int blk) {
    const float numel = (float)K * (float)K * (float)K;
    int idx = blk * 256 + threadIdx.x;
    if (idx >= N3) return 0.f;
    int o2 = idx % O;
    int r  = idx / O;
    int o1 = r % O;  r /= O;
    int o0 = r % O;
    int b  = r / O;
    int inbase = ((b * NZ + B0 * o0) * O + o1) * O + o2;
    const int tapstride = TS * O * O;
    float acc[5];
#pragma unroll
    for (int f = 0; f < 5; f++) {
        const float* p = g_bufB + OFF + f * FS + inbase;
        float a = 0.f;
#pragma unroll
        for (int t = 0; t < K; t++) a += p[t * tapstride];
        acc[f] = a;
    }
    return lncc_eval(acc[0], acc[1], acc[2], acc[3], acc[4], numel);
}

__device__ __forceinline__ float pass34_strip0(int blk) {
    int idx = blk * 256 + threadIdx.x;
    if (idx >= NT0S) return 0.f;
    int o2 = idx % O0;
    int r  = idx / O0;
    int o1 = r % O0;  r /= O0;
    int strip = r % NSTRIP0;
    int b     = r / NSTRIP0;
    int o0s = strip * STRIP0;
    int o0e = (o0s + STRIP0 < O0) ? o0s + STRIP0 : O0;
    const int PS = O0 * O0;
    int base = ((b * NZ0) * O0 + o1) * O0 + o2;
    const float* p0 = g_bufB + OFF0 + base;
    float a0 = 0.f, a1 = 0.f, a2 = 0.f, a3 = 0.f, a4 = 0.f;
    float vsum = 0.f;
    for (int z = o0s; z < o0e + 9; z++) {
        int off = z * PS;
        a0 += p0[off];
        a1 += p0[off + 1 * FS0];
        a2 += p0[off + 2 * FS0];
        a3 += p0[off + 3 * FS0];
        a4 += p0[off + 4 * FS0];
        if (z >= o0s + 9) {
            vsum += lncc_eval(a0, a1, a2, a3, a4, 1000.0f);
            int offt = (z - 9) * PS;
            a0 -= p0[offt];
            a1 -= p0[offt + 1 * FS0];
            a2 -= p0[offt + 2 * FS0];
            a3 -= p0[offt + 3 * FS0];
            a4 -= p0[offt + 4 * FS0];
        }
    }
    return vsum;
}

__global__ __launch_bounds__(256) void pass34_all(float* __restrict__ out) {
    int bb = blockIdx.x;
    float v;
    int pslot;
    if (bb < NBLK0S) {
        v = pass34_strip0(bb);
        pslot = PB0 + bb;
    } else if (bb < NBLK0S + NBLK1) {
        v = pass34_gather<20, O1, NZ1c, 5, 2, OFF1, FS1, N3_1>(bb - NBLK0S);
        pslot = PB1 + (bb - NBLK0S);
    } else {
        v = pass34_gather<40, O2, NZ2, 5, 1, OFF2, FS2, N3_2>(bb - NBLK0S - NBLK1);
        pslot = PB2 + (bb - NBLK0S - NBLK1);
    }

    __shared__ float wsum[8];
    int lane = threadIdx.x & 31;
    int wid  = threadIdx.x >> 5;
#pragma unroll
    for (int o = 16; o > 0; o >>= 1) v += __shfl_down_sync(0xffffffffu, v, o);
    if (lane == 0) wsum[wid] = v;
    __syncthreads();
    if (wid == 0) {
        v = (lane < 8) ? wsum[lane] : 0.f;
#pragma unroll
        for (int o = 4; o > 0; o >>= 1) v += __shfl_down_sync(0xffffffffu, v, o);
        if (lane == 0) g_partials[pslot] = v;
    }

    __shared__ bool isLast;
    __threadfence();
    if (threadIdx.x == 0) {
        unsigned int old = atomicAdd(&g_count, 1u);
        isLast = (old == TOTBLK - 1);
    }
    __syncthreads();
    if (!isLast) return;
    __threadfence();

    __shared__ float sh[256];
    const int   pbase[3] = {PB0, PB1, PB2};
    const int   nblk[3]  = {NBLK0S, NBLK1, NBLK2};
    const float ninv[3]  = {1.0f / N3_0, 1.0f / N3_1, 1.0f / N3_2};
    const float wsc[3]   = {0.1f, 0.3f, 0.6f};
    float total = 0.f;
    for (int sc = 0; sc < 3; sc++) {
        float a = 0.f;
        for (int i = threadIdx.x; i < nblk[sc]; i += 256) a += g_partials[pbase[sc] + i];
        sh[threadIdx.x] = a;
        __syncthreads();
#pragma unroll
        for (int st = 128; st > 0; st >>= 1) {
            if (threadIdx.x < st) sh[threadIdx.x] += sh[threadIdx.x + st];
            __syncthreads();
        }
        if (threadIdx.x == 0) total += (1.0f - sh[0] * ninv[sc]) * wsc[sc];
        __syncthreads();
    }
    if (threadIdx.x == 0) {
        out[0] = total;
        g_count = 0;
    }
}

extern "C" void kernel_launch(void* const* d_in, const int* in_sizes, int n_in,
                              void* d_out, int out_size) {
    const float* x = (const float*)d_in[0];
    const float* y = (const float*)d_in[1];
    float* out = (float*)d_out;

    cudaFuncSetAttribute(fused_all,
                         cudaFuncAttributeMaxDynamicSharedMemorySize, SMEM_ALL);

    fused_all<<<GALL, 512, SMEM_ALL>>>(x, y);
    pass34_all<<<TOTBLK, 256>>>(out);
}